// round 1
// baseline (speedup 1.0000x reference)
#include <cuda_runtime.h>

// ---------------- problem constants ----------------
#define NFFT   64
#define HOP    32
#define PADD   32
#define NFREQ  33          // rfft bins
#define FC     66          // 33 freqs x {re, im}
#define BATCH  8
#define CIN    64
#define COUT   64
#define TLEN   16384
#define NFRAME 513         // (16384 + 64 - 64)/32 + 1
#define NFS    520         // padded frame stride (mult of 8)
#define MS     (BATCH*NFS) // 4160 = 65 * 64 exactly
#define LPAD   68          // smem row pad (floats)

// ---------------- scratch (device globals; zero-initialized once) -------------
__device__ float g_U [FC * CIN  * MS];            // [fc][i][m]   ~70 MB
__device__ float g_Y [FC * COUT * MS];            // [fc][o][m]   ~70 MB
__device__ float g_yf[BATCH * COUT * NFRAME * NFFT]; // [b][o][n][t'] ~67 MB

// =====================================================================
// Stage 1: STFT.  U[fc][i][m] = sum_t  Bw[t][fc] * frame[b,i,n][t]
//   Bw[t][2f+0] =  w[t] * cos(2*pi*f*t/64)
//   Bw[t][2f+1] = -w[t] * sin(2*pi*f*t/64)
// block: (16,17) = 272 thr, tile: fc(68) x dn(64), K = 64 (t)
// grid: (9 n-chunks, 64 i, 8 b)
// =====================================================================
__global__ __launch_bounds__(272) void k_stft(const float* __restrict__ x) {
    const int nch = blockIdx.x, i = blockIdx.y, b = blockIdx.z;
    const int n0 = nch * 64;

    __shared__ __align__(16) float xs[64][LPAD];   // [t][dn]
    __shared__ __align__(16) float Bs[64][LPAD];   // [t][fc]

    const int tx  = threadIdx.x;        // 0..15 -> dn
    const int ty  = threadIdx.y;        // 0..16 -> fc
    const int tid = ty * 16 + tx;       // 0..271

    // build window*DFT matrix
    for (int idx = tid; idx < 64 * LPAD; idx += 272) {
        int t = idx / LPAD, fc = idx % LPAD;
        float v = 0.f;
        if (fc < FC) {
            int f = fc >> 1;
            float s, c;
            sincospif((float)(f * t) / 32.0f, &s, &c);
            v = (fc & 1) ? -s : c;
            float w = 0.5f - 0.5f * cospif((float)t / 32.0f);
            v *= w;
        }
        Bs[t][fc] = v;
    }

    // stage frames into smem, transposed [t][dn], with reflect padding
    const float* xr = x + ((size_t)b * CIN + i) * TLEN;
    for (int s = tid; s < 2080; s += 272) {       // samples covering 64 frames
        int src = n0 * HOP + s - PADD;
        if (src < 0)      src = -src;
        if (src >= TLEN)  src = 2 * TLEN - 2 - src;
        float v = xr[src];
        int dn = s >> 5, t = s & 31;
        if (dn < 64) xs[t][dn] = v;               // first frame containing s
        if (dn >= 1) xs[t + 32][dn - 1] = v;      // previous (overlapping) frame
    }
    __syncthreads();

    // 4x4 register-tiled GEMM over K = 64
    float acc[4][4] = {};
    const int dn0 = tx * 4, fc0 = ty * 4;
#pragma unroll 8
    for (int t = 0; t < 64; t++) {
        float4 av = *reinterpret_cast<const float4*>(&xs[t][dn0]);
        float4 bv = *reinterpret_cast<const float4*>(&Bs[t][fc0]);
        float a[4] = {av.x, av.y, av.z, av.w};
        float bb[4] = {bv.x, bv.y, bv.z, bv.w};
#pragma unroll
        for (int j = 0; j < 4; j++)
#pragma unroll
            for (int k = 0; k < 4; k++)
                acc[j][k] += bb[j] * a[k];
    }

    // store U[fc][i][m], m = b*NFS + n
    const int m_base = b * NFS + n0;
#pragma unroll
    for (int j = 0; j < 4; j++) {
        int fc = fc0 + j;
        if (fc >= FC) break;
        float* dst = g_U + ((size_t)fc * CIN + i) * MS + m_base + dn0;
        if (n0 + dn0 + 3 < NFRAME) {
            *reinterpret_cast<float4*>(dst) =
                make_float4(acc[j][0], acc[j][1], acc[j][2], acc[j][3]);
        } else {
#pragma unroll
            for (int k = 0; k < 4; k++)
                if (n0 + dn0 + k < NFRAME) dst[k] = acc[j][k];
        }
    }
}

// =====================================================================
// Stage 2: mixing.  Y[fc][o][m] = sum_i W[o][i][f] * U[fc][i][m]
// block: (16,16) = 256 thr, tile: o(64) x m(64), K = 64 (i)
// grid: (65 m-tiles, 66 fc)
// =====================================================================
__global__ __launch_bounds__(256) void k_mix(const float* __restrict__ weight) {
    const int m0 = blockIdx.x * 64;
    const int fc = blockIdx.y;
    const int f  = fc >> 1;

    __shared__ __align__(16) float Us[64][LPAD];   // [i][m_local]
    __shared__ __align__(16) float Ws[64][LPAD];   // [i][o]

    const int tx  = threadIdx.x;    // -> m
    const int ty  = threadIdx.y;    // -> o
    const int tid = ty * 16 + tx;

    // load W_f (transposed to [i][o]) and U tile
    for (int idx = tid; idx < 64 * 64; idx += 256) {
        int o = idx >> 6, i = idx & 63;
        Ws[i][o] = weight[((size_t)o * CIN + i) * NFREQ + f];
    }
    const float* Usrc = g_U + (size_t)fc * CIN * MS + m0;
    for (int idx = tid; idx < 64 * 64; idx += 256) {
        int i = idx >> 6, c = idx & 63;
        Us[i][c] = Usrc[(size_t)i * MS + c];
    }
    __syncthreads();

    float acc[4][4] = {};
    const int c0 = tx * 4, o0 = ty * 4;
#pragma unroll 8
    for (int i = 0; i < 64; i++) {
        float4 av = *reinterpret_cast<const float4*>(&Us[i][c0]);
        float4 bv = *reinterpret_cast<const float4*>(&Ws[i][o0]);
        float a[4] = {av.x, av.y, av.z, av.w};
        float bb[4] = {bv.x, bv.y, bv.z, bv.w};
#pragma unroll
        for (int j = 0; j < 4; j++)
#pragma unroll
            for (int k = 0; k < 4; k++)
                acc[j][k] += bb[j] * a[k];
    }

    float* Ybase = g_Y + (size_t)fc * COUT * MS + m0;
#pragma unroll
    for (int j = 0; j < 4; j++) {
        float* dst = Ybase + (size_t)(o0 + j) * MS + c0;
        *reinterpret_cast<float4*>(dst) =
            make_float4(acc[j][0], acc[j][1], acc[j][2], acc[j][3]);
    }
}

// =====================================================================
// Stage 3: ISTFT frames.
//   yf[b][o][n][t'] = sum_fc  ID[fc][t'] * Y[fc][o][m],  m = b*NFS + n
//   ID[2f+0][t'] =  w[t'] * a_f * cos(2*pi*f*t'/64) / 64
//   ID[2f+1][t'] = -w[t'] * a_f * sin(2*pi*f*t'/64) / 64   (0 for f=0,32)
//   a_f = 1 for f in {0,32}, else 2
// block: (16,16), tile: m(64) x t'(64), K = 66 (fc)
// grid: (65 m-tiles, 64 o)
// =====================================================================
__global__ __launch_bounds__(256) void k_frames() {
    const int m0 = blockIdx.x * 64;
    const int o  = blockIdx.y;

    __shared__ __align__(16) float Ys[FC][LPAD];   // [fc][m_local]
    __shared__ __align__(16) float IDs[FC][LPAD];  // [fc][t']

    const int tx  = threadIdx.x;    // -> t'
    const int ty  = threadIdx.y;    // -> m
    const int tid = ty * 16 + tx;

    // build inverse-DFT * window matrix
    for (int idx = tid; idx < FC * LPAD; idx += 256) {
        int fc = idx / LPAD, t = idx % LPAD;
        float v = 0.f;
        if (t < 64) {
            int f = fc >> 1;
            float s, c;
            sincospif((float)(f * t) / 32.0f, &s, &c);
            float af = (f == 0 || f == 32) ? 1.0f : 2.0f;
            if (fc & 1) {
                v = (f == 0 || f == 32) ? 0.f : -s * af;
            } else {
                v = c * af;
            }
            float w = 0.5f - 0.5f * cospif((float)t / 32.0f);
            v *= w * (1.0f / 64.0f);
        }
        IDs[fc][t] = v;
    }
    // load Y tile [fc][m_local]
    const float* Ysrc = g_Y + (size_t)o * MS + m0;
    for (int idx = tid; idx < FC * 64; idx += 256) {
        int fc = idx >> 6, c = idx & 63;
        Ys[fc][c] = Ysrc[(size_t)fc * COUT * MS + c];
    }
    __syncthreads();

    float acc[4][4] = {};
    const int t0 = tx * 4, r0 = ty * 4;   // r0 -> m_local
#pragma unroll 6
    for (int fc = 0; fc < FC; fc++) {
        float4 av = *reinterpret_cast<const float4*>(&Ys[fc][r0]);
        float4 bv = *reinterpret_cast<const float4*>(&IDs[fc][t0]);
        float a[4] = {av.x, av.y, av.z, av.w};
        float bb[4] = {bv.x, bv.y, bv.z, bv.w};
#pragma unroll
        for (int j = 0; j < 4; j++)      // j -> m
#pragma unroll
            for (int k = 0; k < 4; k++)  // k -> t'
                acc[j][k] += a[j] * bb[k];
    }

#pragma unroll
    for (int j = 0; j < 4; j++) {
        int m = m0 + r0 + j;
        int b = m / NFS;
        int n = m - b * NFS;
        if (n < NFRAME) {
            float* dst = g_yf +
                (((size_t)b * COUT + o) * NFRAME + n) * NFFT + t0;
            *reinterpret_cast<float4*>(dst) =
                make_float4(acc[j][0], acc[j][1], acc[j][2], acc[j][3]);
        }
    }
}

// =====================================================================
// Stage 4: overlap-add gather + envelope normalization.
// Each output sample gets exactly 2 frame taps.
// =====================================================================
__global__ __launch_bounds__(256) void k_ola(float* __restrict__ out) {
    int idx = blockIdx.x * 256 + threadIdx.x;          // over B*COUT*T
    int t  = idx & (TLEN - 1);
    int bo = idx >> 14;
    int tp = t + PADD;
    int nh = tp >> 5;
    int r  = tp & 31;
    const float* yf = g_yf + (size_t)bo * NFRAME * NFFT;
    float v = yf[(size_t)nh * NFFT + r] + yf[(size_t)(nh - 1) * NFFT + r + 32];
    float w1 = 0.5f - 0.5f * cospif((float)r / 32.0f);
    float w2 = 0.5f + 0.5f * cospif((float)r / 32.0f);  // w[r+32]
    out[idx] = v / (w1 * w1 + w2 * w2);
}

// =====================================================================
extern "C" void kernel_launch(void* const* d_in, const int* in_sizes, int n_in,
                              void* d_out, int out_size) {
    const float* x      = (const float*)d_in[0];   // [8,64,16384]
    const float* weight = (const float*)d_in[1];   // [64,64,33]
    float* out          = (float*)d_out;           // [8,64,16384]

    (void)in_sizes; (void)n_in; (void)out_size;

    k_stft  <<<dim3(9, CIN, BATCH), dim3(16, 17)>>>(x);
    k_mix   <<<dim3(MS / 64, FC),   dim3(16, 16)>>>(weight);
    k_frames<<<dim3(MS / 64, COUT), dim3(16, 16)>>>();
    k_ola   <<<(BATCH * COUT * TLEN) / 256, 256>>>(out);
}

// round 2
// speedup vs baseline: 1.5885x; 1.5885x over previous
#include <cuda_runtime.h>
#include <stdint.h>

// ---------------- problem constants ----------------
#define NFFT   64
#define HOP    32
#define PADD   32
#define NFREQ  33          // rfft bins
#define FC     66          // 33 freqs x {re, im}
#define BATCH  8
#define CIN    64
#define COUT   64
#define TLEN   16384
#define NFRAME 513
#define NFS    544         // padded frame stride (so MS is a multiple of 128)
#define MS     (BATCH*NFS) // 4352 = 34 * 128
#define C2     (2*MS)      // 8704 = 68 * 128  (re/im stacked columns)

// ---------------- scratch (device globals; zero-initialized at load) ---------
__device__ float g_U [(size_t)NFREQ * CIN  * C2];              // [f][i][part*MS+m]
__device__ float g_Y [(size_t)NFREQ * COUT * C2];              // [f][o][part*MS+m]
__device__ float g_yf[(size_t)BATCH * COUT * NFRAME * NFFT];   // [b*64+o][n][t']

union LF { long long ll; float2 f2; };

__device__ __forceinline__ long long dupf(float v) {
    unsigned u = __float_as_uint(v);
    long long r;
    asm("mov.b64 %0, {%1, %1};" : "=l"(r) : "r"(u));
    return r;
}
__device__ __forceinline__ void ffma2(long long& d, long long a, long long b) {
    asm("fma.rn.f32x2 %0, %1, %2, %0;" : "+l"(d) : "l"(a), "l"(b));
}

// =====================================================================
// Stage 1: STFT.  U[fc][c] = sum_t B[t][fc] * frames[t][c]
// tile: fc(72) x c(128 = 2 chan x 64 frames), K staged in 2 halves of 32
// block (16,18)=288thr, micro 4(fc) x 8(c) via 16 FFMA2
// grid (9 n-tiles, 32 i-pairs, 8 b)
// =====================================================================
__global__ __launch_bounds__(288) void k_stft(const float* __restrict__ x) {
    const int nch = blockIdx.x, ip = blockIdx.y, b = blockIdx.z;
    const int n0 = nch * 64;
    const int i0 = ip * 2;

    __shared__ __align__(16) float Bs[64][72];
    __shared__ __align__(16) float xs[32][136];

    const int tx = threadIdx.x, ty = threadIdx.y;
    const int tid = ty * 16 + tx;

    // build window*DFT matrix (rows t, cols fc)
    for (int idx = tid; idx < 64 * 72; idx += 288) {
        int t = idx / 72, fc = idx % 72;
        float v = 0.f;
        if (fc < FC) {
            int f = fc >> 1;
            float s, c;
            sincospif((float)(f * t) / 32.0f, &s, &c);
            v = (fc & 1) ? -s : c;
            v *= 0.5f - 0.5f * cospif((float)t / 32.0f);
        }
        Bs[t][fc] = v;
    }

    const int c0  = tx * 8;
    const int il  = c0 >> 6;       // which channel of the pair
    const int nl0 = c0 & 63;       // frame offset within tile
    const int fc0 = ty * 4;

    long long acc[4][4] = {};      // [fc][c-pair]

    const float* xr0 = x + ((size_t)b * CIN + i0) * TLEN;

    for (int h = 0; h < 2; h++) {
        __syncthreads();
        // stage half-K frames: xs[tt][il*68+n] = x[n0*32 + (n+h)*32 + tt - 32]
        for (int il2 = 0; il2 < 2; il2++) {
            const float* xr = xr0 + (size_t)il2 * TLEN;
            for (int sidx = tid; sidx < 2048; sidx += 288) {
                int src = n0 * HOP + h * 32 + sidx - PADD;
                if (src < 0)     src = -src;
                if (src >= TLEN) src = 2 * TLEN - 2 - src;
                xs[sidx & 31][il2 * 68 + (sidx >> 5)] = xr[src];
            }
        }
        __syncthreads();

#pragma unroll 8
        for (int tt = 0; tt < 32; tt++) {
            const float* ap = &xs[tt][il * 68 + nl0];
            longlong2 A0 = *(const longlong2*)ap;
            longlong2 A1 = *(const longlong2*)(ap + 4);
            float4 bq = *(const float4*)&Bs[h * 32 + tt][fc0];
            long long b0 = dupf(bq.x), b1 = dupf(bq.y), b2 = dupf(bq.z), b3 = dupf(bq.w);
            ffma2(acc[0][0], A0.x, b0); ffma2(acc[0][1], A0.y, b0);
            ffma2(acc[0][2], A1.x, b0); ffma2(acc[0][3], A1.y, b0);
            ffma2(acc[1][0], A0.x, b1); ffma2(acc[1][1], A0.y, b1);
            ffma2(acc[1][2], A1.x, b1); ffma2(acc[1][3], A1.y, b1);
            ffma2(acc[2][0], A0.x, b2); ffma2(acc[2][1], A0.y, b2);
            ffma2(acc[2][2], A1.x, b2); ffma2(acc[2][3], A1.y, b2);
            ffma2(acc[3][0], A0.x, b3); ffma2(acc[3][1], A0.y, b3);
            ffma2(acc[3][2], A1.x, b3); ffma2(acc[3][3], A1.y, b3);
        }
    }

    // store U
    const int nb = n0 + nl0;
#pragma unroll
    for (int j = 0; j < 4; j++) {
        int fc = fc0 + j;
        if (fc >= FC) continue;
        int f = fc >> 1, part = fc & 1;
        float* dst = g_U + ((size_t)f * CIN + (i0 + il)) * C2
                         + (size_t)part * MS + (size_t)b * NFS + nb;
        LF p0, p1, p2, p3;
        p0.ll = acc[j][0]; p1.ll = acc[j][1]; p2.ll = acc[j][2]; p3.ll = acc[j][3];
        if (nb + 7 < NFRAME) {
            *(float4*)dst       = make_float4(p0.f2.x, p0.f2.y, p1.f2.x, p1.f2.y);
            *(float4*)(dst + 4) = make_float4(p2.f2.x, p2.f2.y, p3.f2.x, p3.f2.y);
        } else {
            float vals[8] = {p0.f2.x, p0.f2.y, p1.f2.x, p1.f2.y,
                             p2.f2.x, p2.f2.y, p3.f2.x, p3.f2.y};
#pragma unroll
            for (int k2 = 0; k2 < 8; k2++)
                if (nb + k2 < NFRAME) dst[k2] = vals[k2];
        }
    }
}

// =====================================================================
// Stage 2: mixing.  Y_f[o][c] = sum_i W_f[i][o] * U_f[i][c]
// tile: o(64) x c(128), K=64 (i) staged in 2 halves
// block (16,16), micro 4(o) x 8(c). grid (68 c-tiles, 33 f)
// =====================================================================
__global__ __launch_bounds__(256) void k_mix(const float* __restrict__ weight) {
    const int c0g = blockIdx.x * 128;
    const int f   = blockIdx.y;

    __shared__ __align__(16) float Ws[64][68];
    __shared__ __align__(16) float Us[32][136];

    const int tx = threadIdx.x, ty = threadIdx.y;
    const int tid = ty * 16 + tx;

    for (int idx = tid; idx < 64 * 64; idx += 256) {
        int o = idx >> 6, i = idx & 63;
        Ws[i][o] = weight[((size_t)o * CIN + i) * NFREQ + f];
    }

    const int c0 = tx * 8, o0 = ty * 4;
    long long acc[4][4] = {};   // [o][c-pair]
    const float* Ubase = g_U + (size_t)f * CIN * C2 + c0g;

    for (int h = 0; h < 2; h++) {
        __syncthreads();
        for (int idx = tid; idx < 32 * 32; idx += 256) {
            int i = idx >> 5, q = idx & 31;
            *(float4*)&Us[i][q * 4] =
                *(const float4*)(Ubase + (size_t)(h * 32 + i) * C2 + q * 4);
        }
        __syncthreads();

#pragma unroll 8
        for (int k = 0; k < 32; k++) {
            const float* ap = &Us[k][c0];
            longlong2 A0 = *(const longlong2*)ap;
            longlong2 A1 = *(const longlong2*)(ap + 4);
            float4 bq = *(const float4*)&Ws[h * 32 + k][o0];
            long long b0 = dupf(bq.x), b1 = dupf(bq.y), b2 = dupf(bq.z), b3 = dupf(bq.w);
            ffma2(acc[0][0], A0.x, b0); ffma2(acc[0][1], A0.y, b0);
            ffma2(acc[0][2], A1.x, b0); ffma2(acc[0][3], A1.y, b0);
            ffma2(acc[1][0], A0.x, b1); ffma2(acc[1][1], A0.y, b1);
            ffma2(acc[1][2], A1.x, b1); ffma2(acc[1][3], A1.y, b1);
            ffma2(acc[2][0], A0.x, b2); ffma2(acc[2][1], A0.y, b2);
            ffma2(acc[2][2], A1.x, b2); ffma2(acc[2][3], A1.y, b2);
            ffma2(acc[3][0], A0.x, b3); ffma2(acc[3][1], A0.y, b3);
            ffma2(acc[3][2], A1.x, b3); ffma2(acc[3][3], A1.y, b3);
        }
    }

    float* Ybase = g_Y + (size_t)f * COUT * C2 + c0g + c0;
#pragma unroll
    for (int j = 0; j < 4; j++) {
        float* dst = Ybase + (size_t)(o0 + j) * C2;
        LF p0, p1, p2, p3;
        p0.ll = acc[j][0]; p1.ll = acc[j][1]; p2.ll = acc[j][2]; p3.ll = acc[j][3];
        *(float4*)dst       = make_float4(p0.f2.x, p0.f2.y, p1.f2.x, p1.f2.y);
        *(float4*)(dst + 4) = make_float4(p2.f2.x, p2.f2.y, p3.f2.x, p3.f2.y);
    }
}

// =====================================================================
// Stage 3: ISTFT frames.  yf[m][t'] = sum_fc ID[fc][t'] * Y[fc][m]
// tile: m(128) x t'(64), K=66 staged in 2 halves of 33
// block (16,16), micro: m-pairs(4) x t'(4). grid (34 m-tiles, 64 o)
// =====================================================================
__global__ __launch_bounds__(256) void k_frames() {
    const int m0g = blockIdx.x * 128;
    const int o   = blockIdx.y;

    __shared__ __align__(16) float IDs[FC][68];
    __shared__ __align__(16) float Ys[33][136];

    const int tx = threadIdx.x, ty = threadIdx.y;
    const int tid = ty * 16 + tx;

    // inverse-DFT * window matrix
    for (int idx = tid; idx < FC * 64; idx += 256) {
        int fc = idx / 64, t = idx % 64;
        int f = fc >> 1;
        float s, c;
        sincospif((float)(f * t) / 32.0f, &s, &c);
        float af = (f == 0 || f == 32) ? 1.0f : 2.0f;
        float v;
        if (fc & 1) v = (f == 0 || f == 32) ? 0.f : -s * af;
        else        v = c * af;
        v *= (0.5f - 0.5f * cospif((float)t / 32.0f)) * (1.0f / 64.0f);
        IDs[fc][t] = v;
    }

    const int t0 = tx * 4, r0 = ty * 8;
    long long acc[4][4] = {};   // [m-pair][t]

    for (int h = 0; h < 2; h++) {
        __syncthreads();
        for (int idx = tid; idx < 33 * 32; idx += 256) {
            int fcl = idx >> 5, q = idx & 31;
            int fc = h * 33 + fcl;
            const float* src = g_Y + ((size_t)(fc >> 1) * COUT + o) * C2
                                   + (size_t)(fc & 1) * MS + m0g + q * 4;
            *(float4*)&Ys[fcl][q * 4] = *(const float4*)src;
        }
        __syncthreads();

#pragma unroll 11
        for (int k = 0; k < 33; k++) {
            const float* ap = &Ys[k][r0];
            longlong2 A0 = *(const longlong2*)ap;
            longlong2 A1 = *(const longlong2*)(ap + 4);
            float4 bq = *(const float4*)&IDs[h * 33 + k][t0];
            long long b0 = dupf(bq.x), b1 = dupf(bq.y), b2 = dupf(bq.z), b3 = dupf(bq.w);
            ffma2(acc[0][0], A0.x, b0); ffma2(acc[0][1], A0.x, b1);
            ffma2(acc[0][2], A0.x, b2); ffma2(acc[0][3], A0.x, b3);
            ffma2(acc[1][0], A0.y, b0); ffma2(acc[1][1], A0.y, b1);
            ffma2(acc[1][2], A0.y, b2); ffma2(acc[1][3], A0.y, b3);
            ffma2(acc[2][0], A1.x, b0); ffma2(acc[2][1], A1.x, b1);
            ffma2(acc[2][2], A1.x, b2); ffma2(acc[2][3], A1.x, b3);
            ffma2(acc[3][0], A1.y, b0); ffma2(acc[3][1], A1.y, b1);
            ffma2(acc[3][2], A1.y, b2); ffma2(acc[3][3], A1.y, b3);
        }
    }

    // acc[p][k]: pair = frames (m0g+r0+2p, +1), t' = t0+k
#pragma unroll
    for (int p = 0; p < 4; p++) {
        int m = m0g + r0 + 2 * p;
        int bb = m / NFS;
        int n  = m - bb * NFS;
        LF q0, q1, q2, q3;
        q0.ll = acc[p][0]; q1.ll = acc[p][1]; q2.ll = acc[p][2]; q3.ll = acc[p][3];
        if (n < NFRAME) {
            float* dst = g_yf + (((size_t)bb * COUT + o) * NFRAME + n) * NFFT + t0;
            *(float4*)dst = make_float4(q0.f2.x, q1.f2.x, q2.f2.x, q3.f2.x);
        }
        if (n + 1 < NFRAME) {
            float* dst = g_yf + (((size_t)bb * COUT + o) * NFRAME + n + 1) * NFFT + t0;
            *(float4*)dst = make_float4(q0.f2.y, q1.f2.y, q2.f2.y, q3.f2.y);
        }
    }
}

// =====================================================================
// Stage 4: overlap-add + envelope normalization (vectorized, table-based)
// =====================================================================
__global__ __launch_bounds__(256) void k_ola(float* __restrict__ out) {
    __shared__ float inv[32];
    int tid = threadIdx.x;
    if (tid < 32) {
        float c = cospif((float)tid / 32.0f);
        float w1 = 0.5f - 0.5f * c, w2 = 0.5f + 0.5f * c;
        inv[tid] = 1.0f / (w1 * w1 + w2 * w2);
    }
    __syncthreads();

    int gid  = blockIdx.x * 256 + tid;
    int eidx = gid * 4;
    int t  = eidx & (TLEN - 1);
    int bo = eidx >> 14;
    int tp = t + PADD;
    int nh = tp >> 5, r = tp & 31;     // r is a multiple of 4, r <= 28
    const float* yf = g_yf + (size_t)bo * NFRAME * NFFT;
    float4 A  = *(const float4*)&yf[(size_t)nh * NFFT + r];
    float4 Bv = *(const float4*)&yf[(size_t)(nh - 1) * NFFT + r + 32];
    float4 o4;
    o4.x = (A.x + Bv.x) * inv[r];
    o4.y = (A.y + Bv.y) * inv[r + 1];
    o4.z = (A.z + Bv.z) * inv[r + 2];
    o4.w = (A.w + Bv.w) * inv[r + 3];
    *(float4*)(out + eidx) = o4;
}

// =====================================================================
extern "C" void kernel_launch(void* const* d_in, const int* in_sizes, int n_in,
                              void* d_out, int out_size) {
    const float* x      = (const float*)d_in[0];   // [8,64,16384]
    const float* weight = (const float*)d_in[1];   // [64,64,33]
    float* out          = (float*)d_out;           // [8,64,16384]
    (void)in_sizes; (void)n_in; (void)out_size;

    k_stft  <<<dim3(9, 32, 8),  dim3(16, 18)>>>(x);
    k_mix   <<<dim3(68, 33),    dim3(16, 16)>>>(weight);
    k_frames<<<dim3(34, 64),    dim3(16, 16)>>>();
    k_ola   <<<(BATCH * COUT * TLEN) / 1024, 256>>>(out);
}

// round 4
// speedup vs baseline: 1.8166x; 1.1436x over previous
#include <cuda_runtime.h>
#include <cuda_bf16.h>
#include <stdint.h>

// ---------------- problem constants ----------------
#define NFFT   64
#define HOP    32
#define PADD   32
#define NFREQ  33
#define FC     66
#define BATCH  8
#define CIN    64
#define COUT   64
#define TLEN   16384
#define NFRAME 513
#define NFS    544
#define MS     (BATCH*NFS)   // 4352
#define C2     (2*MS)        // 8704 = 68*128

// ---------------- scratch ----------------
__device__ float g_U[(size_t)NFREQ * CIN  * C2];   // [f][i][c]
__device__ float g_Y[(size_t)NFREQ * COUT * C2];   // [f][o][c]
__device__ __nv_bfloat16 g_Wb[(size_t)NFREQ * 2 * COUT * CIN]; // [f][part][o][i]

union LF { long long ll; float2 f2; };

__device__ __forceinline__ long long dupf(float v) {
    unsigned u = __float_as_uint(v);
    long long r;
    asm("mov.b64 %0, {%1, %1};" : "=l"(r) : "r"(u));
    return r;
}
__device__ __forceinline__ void ffma2(long long& d, long long a, long long b) {
    asm("fma.rn.f32x2 %0, %1, %2, %0;" : "+l"(d) : "l"(a), "l"(b));
}
__device__ __forceinline__ void mma_bf16(float* d, const uint32_t* a, const uint32_t* b) {
    asm volatile(
        "mma.sync.aligned.m16n8k16.row.col.f32.bf16.bf16.f32 "
        "{%0,%1,%2,%3}, {%4,%5,%6,%7}, {%8,%9}, {%0,%1,%2,%3};"
        : "+f"(d[0]), "+f"(d[1]), "+f"(d[2]), "+f"(d[3])
        : "r"(a[0]), "r"(a[1]), "r"(a[2]), "r"(a[3]), "r"(b[0]), "r"(b[1]));
}

// =====================================================================
// Stage 0: split weight into bf16 hi/lo, layout [f][part][o][i]
// =====================================================================
__global__ __launch_bounds__(256) void k_wprep(const float* __restrict__ weight) {
    int gid = blockIdx.x * 256 + threadIdx.x;
    if (gid >= NFREQ * COUT * CIN) return;
    int f = gid / (COUT * CIN);
    int rem = gid - f * (COUT * CIN);
    int o = rem >> 6, i = rem & 63;
    float w = weight[((size_t)o * CIN + i) * NFREQ + f];
    __nv_bfloat16 hi = __float2bfloat16(w);
    __nv_bfloat16 lo = __float2bfloat16(w - __bfloat162float(hi));
    size_t base = ((size_t)f * 2) * COUT * CIN + (size_t)o * CIN + i;
    g_Wb[base] = hi;
    g_Wb[base + (size_t)COUT * CIN] = lo;
}

// =====================================================================
// Stage 1: STFT (FFMA2 path)
// =====================================================================
__global__ __launch_bounds__(288) void k_stft(const float* __restrict__ x) {
    const int nch = blockIdx.x, ip = blockIdx.y, b = blockIdx.z;
    const int n0 = nch * 64;
    const int i0 = ip * 2;

    __shared__ __align__(16) float Bs[64][72];
    __shared__ __align__(16) float xs[32][136];

    const int tx = threadIdx.x, ty = threadIdx.y;
    const int tid = ty * 16 + tx;

    for (int idx = tid; idx < 64 * 72; idx += 288) {
        int t = idx / 72, fc = idx % 72;
        float v = 0.f;
        if (fc < FC) {
            int f = fc >> 1;
            float s, c;
            sincospif((float)(f * t) / 32.0f, &s, &c);
            v = (fc & 1) ? -s : c;
            v *= 0.5f - 0.5f * cospif((float)t / 32.0f);
        }
        Bs[t][fc] = v;
    }

    const int c0 = tx * 8;
    const int il = c0 >> 6, nl0 = c0 & 63;
    const int fc0 = ty * 4;

    long long acc[4][4] = {};
    const float* xr0 = x + ((size_t)b * CIN + i0) * TLEN;

    for (int h = 0; h < 2; h++) {
        __syncthreads();
        for (int il2 = 0; il2 < 2; il2++) {
            const float* xr = xr0 + (size_t)il2 * TLEN;
            for (int sidx = tid; sidx < 2048; sidx += 288) {
                int src = n0 * HOP + h * 32 + sidx - PADD;
                if (src < 0)     src = -src;
                if (src >= TLEN) src = 2 * TLEN - 2 - src;
                xs[sidx & 31][il2 * 68 + (sidx >> 5)] = xr[src];
            }
        }
        __syncthreads();

#pragma unroll 8
        for (int tt = 0; tt < 32; tt++) {
            const float* ap = &xs[tt][il * 68 + nl0];
            longlong2 A0 = *(const longlong2*)ap;
            longlong2 A1 = *(const longlong2*)(ap + 4);
            float4 bq = *(const float4*)&Bs[h * 32 + tt][fc0];
            long long b0 = dupf(bq.x), b1 = dupf(bq.y), b2 = dupf(bq.z), b3 = dupf(bq.w);
            ffma2(acc[0][0], A0.x, b0); ffma2(acc[0][1], A0.y, b0);
            ffma2(acc[0][2], A1.x, b0); ffma2(acc[0][3], A1.y, b0);
            ffma2(acc[1][0], A0.x, b1); ffma2(acc[1][1], A0.y, b1);
            ffma2(acc[1][2], A1.x, b1); ffma2(acc[1][3], A1.y, b1);
            ffma2(acc[2][0], A0.x, b2); ffma2(acc[2][1], A0.y, b2);
            ffma2(acc[2][2], A1.x, b2); ffma2(acc[2][3], A1.y, b2);
            ffma2(acc[3][0], A0.x, b3); ffma2(acc[3][1], A0.y, b3);
            ffma2(acc[3][2], A1.x, b3); ffma2(acc[3][3], A1.y, b3);
        }
    }

    const int nb = n0 + nl0;
#pragma unroll
    for (int j = 0; j < 4; j++) {
        int fc = fc0 + j;
        if (fc >= FC) continue;
        int f = fc >> 1, part = fc & 1;
        float* dst = g_U + ((size_t)f * CIN + (i0 + il)) * C2
                         + (size_t)part * MS + (size_t)b * NFS + nb;
        LF p0, p1, p2, p3;
        p0.ll = acc[j][0]; p1.ll = acc[j][1]; p2.ll = acc[j][2]; p3.ll = acc[j][3];
        if (nb + 7 < NFRAME) {
            *(float4*)dst       = make_float4(p0.f2.x, p0.f2.y, p1.f2.x, p1.f2.y);
            *(float4*)(dst + 4) = make_float4(p2.f2.x, p2.f2.y, p3.f2.x, p3.f2.y);
        } else {
            float vals[8] = {p0.f2.x, p0.f2.y, p1.f2.x, p1.f2.y,
                             p2.f2.x, p2.f2.y, p3.f2.x, p3.f2.y};
#pragma unroll
            for (int k2 = 0; k2 < 8; k2++)
                if (nb + k2 < NFRAME) dst[k2] = vals[k2];
        }
    }
}

// =====================================================================
// Stage 2: mix via mma.sync bf16 (3-pass split precision)
// Y_f[o][c] = sum_i W_f[o][i] * U_f[i][c];  M=c(128), N=o(64), K=i(64)
// smem (dynamic, 52224 B):
//   A_hi[128][68]bf16 @0, A_lo @17408, B_hi[64][68]bf16 @34816, B_lo @43520
// 8 warps: warp (wm=w&3, wn=w>>2) covers m[wm*32,+32) x n[wn*32,+32)
// =====================================================================
#define MIX_SMEM 52224
#define AH_OFF 0
#define AL_OFF 17408
#define BH_OFF 34816
#define BL_OFF 43520

__global__ __launch_bounds__(256) void k_mix_mma() {
    extern __shared__ __align__(16) char sm[];
    const int tid = threadIdx.x;
    const int w = tid >> 5, lane = tid & 31;
    const int g = lane >> 2, tig = lane & 3;
    const int c0g = blockIdx.x * 128;
    const int f   = blockIdx.y;

    // stage A = U tile (convert fp32 -> bf16 hi/lo), layout [m=c][k=i], pad 68
    const float* Ub = g_U + (size_t)f * CIN * C2 + c0g;
    for (int idx = tid; idx < 8192; idx += 256) {
        int i = idx >> 7, c = idx & 127;
        float v = Ub[(size_t)i * C2 + c];
        __nv_bfloat16 hi = __float2bfloat16(v);
        __nv_bfloat16 lo = __float2bfloat16(v - __bfloat162float(hi));
        int off = c * 136 + i * 2;
        *(__nv_bfloat16*)(sm + AH_OFF + off) = hi;
        *(__nv_bfloat16*)(sm + AL_OFF + off) = lo;
    }
    // stage B = W_f (pre-split), layout [n=o][k=i], pad 68
    {
        const uint32_t* Wh = (const uint32_t*)(g_Wb + ((size_t)f * 2) * COUT * CIN);
        const uint32_t* Wl = Wh + (COUT * CIN) / 2;
        for (int idx = tid; idx < 2048; idx += 256) {
            int o = idx >> 5, ip = idx & 31;
            int off = o * 136 + ip * 4;
            *(uint32_t*)(sm + BH_OFF + off) = Wh[o * 32 + ip];
            *(uint32_t*)(sm + BL_OFF + off) = Wl[o * 32 + ip];
        }
    }
    __syncthreads();

    const int m_base = (w & 3) * 32;
    const int n_base = (w >> 2) * 32;

    float d[8][4] = {};   // [r*4 + cdx][slot]

#pragma unroll
    for (int kc = 0; kc < 4; kc++) {
        const int k0 = kc * 16;
        uint32_t ah[2][4], al[2][4], bh[4][2], bl[4][2];
#pragma unroll
        for (int r = 0; r < 2; r++) {
            int m = m_base + r * 16 + g;
            int cb = k0 * 2 + tig * 4;
            ah[r][0] = *(const uint32_t*)(sm + AH_OFF + m * 136 + cb);
            ah[r][1] = *(const uint32_t*)(sm + AH_OFF + (m + 8) * 136 + cb);
            ah[r][2] = *(const uint32_t*)(sm + AH_OFF + m * 136 + cb + 16);
            ah[r][3] = *(const uint32_t*)(sm + AH_OFF + (m + 8) * 136 + cb + 16);
            al[r][0] = *(const uint32_t*)(sm + AL_OFF + m * 136 + cb);
            al[r][1] = *(const uint32_t*)(sm + AL_OFF + (m + 8) * 136 + cb);
            al[r][2] = *(const uint32_t*)(sm + AL_OFF + m * 136 + cb + 16);
            al[r][3] = *(const uint32_t*)(sm + AL_OFF + (m + 8) * 136 + cb + 16);
        }
#pragma unroll
        for (int cdx = 0; cdx < 4; cdx++) {
            int n = n_base + cdx * 8 + g;
            int cb = k0 * 2 + tig * 4;
            bh[cdx][0] = *(const uint32_t*)(sm + BH_OFF + n * 136 + cb);
            bh[cdx][1] = *(const uint32_t*)(sm + BH_OFF + n * 136 + cb + 16);
            bl[cdx][0] = *(const uint32_t*)(sm + BL_OFF + n * 136 + cb);
            bl[cdx][1] = *(const uint32_t*)(sm + BL_OFF + n * 136 + cb + 16);
        }
#pragma unroll
        for (int r = 0; r < 2; r++)
#pragma unroll
            for (int cdx = 0; cdx < 4; cdx++) {
                mma_bf16(d[r * 4 + cdx], ah[r], bh[cdx]);
                mma_bf16(d[r * 4 + cdx], al[r], bh[cdx]);
                mma_bf16(d[r * 4 + cdx], ah[r], bl[cdx]);
            }
    }

    // store: D[m][n] -> g_Y[f][o=n][c0g + m]
    float* Yf = g_Y + (size_t)f * COUT * C2 + c0g;
#pragma unroll
    for (int r = 0; r < 2; r++)
#pragma unroll
        for (int cdx = 0; cdx < 4; cdx++) {
            const float* dd = d[r * 4 + cdx];
            int m = m_base + r * 16 + g;
            int n = n_base + cdx * 8 + tig * 2;
            float* p = Yf + (size_t)n * C2 + m;
            p[0]          = dd[0];
            p[C2]         = dd[1];
            p[8]          = dd[2];
            p[C2 + 8]     = dd[3];
        }
}

// =====================================================================
// Stage 3+4 fused: ISTFT frames + OLA + env normalization (FFMA2)
// =====================================================================
__global__ __launch_bounds__(256) void k_frames_ola(float* __restrict__ out) {
    __shared__ __align__(16) float R[8976];
    __shared__ float yc[66];
    __shared__ float inv[32];
    float* IDs = R;               // IDs[fc*68 + t]
    float* Ys  = R + 4488;        // Ys[k*136 + q]

    const int m0g = blockIdx.x * 128;
    const int o   = blockIdx.y;
    const int tx = threadIdx.x, ty = threadIdx.y;
    const int tid = ty * 16 + tx;

    for (int idx = tid; idx < FC * 64; idx += 256) {
        int fc = idx / 64, t = idx % 64;
        int f = fc >> 1;
        float s, c;
        sincospif((float)(f * t) / 32.0f, &s, &c);
        float af = (f == 0 || f == 32) ? 1.0f : 2.0f;
        float v;
        if (fc & 1) v = (f == 0 || f == 32) ? 0.f : -s * af;
        else        v = c * af;
        v *= (0.5f - 0.5f * cospif((float)t / 32.0f)) * (1.0f / 64.0f);
        IDs[fc * 68 + t] = v;
    }
    if (tid < 66) {
        yc[tid] = (m0g > 0)
            ? g_Y[((size_t)(tid >> 1) * COUT + o) * C2 + (size_t)(tid & 1) * MS + m0g - 1]
            : 0.f;
    }
    if (tid < 32) {
        float c = cospif((float)tid / 32.0f);
        float w1 = 0.5f - 0.5f * c, w2 = 0.5f + 0.5f * c;
        inv[tid] = 1.0f / (w1 * w1 + w2 * w2);
    }

    const int t0 = tx * 4, r0 = ty * 8;
    long long acc[4][4] = {};

    for (int h = 0; h < 2; h++) {
        __syncthreads();
        for (int idx = tid; idx < 33 * 32; idx += 256) {
            int fcl = idx >> 5, q = idx & 31;
            int fc = h * 33 + fcl;
            const float* src = g_Y + ((size_t)(fc >> 1) * COUT + o) * C2
                                   + (size_t)(fc & 1) * MS + m0g + q * 4;
            *(float4*)&Ys[fcl * 136 + q * 4] = *(const float4*)src;
        }
        __syncthreads();

#pragma unroll 11
        for (int k = 0; k < 33; k++) {
            const float* ap = &Ys[k * 136 + r0];
            longlong2 A0 = *(const longlong2*)ap;
            longlong2 A1 = *(const longlong2*)(ap + 4);
            float4 bq = *(const float4*)&IDs[(h * 33 + k) * 68 + t0];
            long long b0 = dupf(bq.x), b1 = dupf(bq.y), b2 = dupf(bq.z), b3 = dupf(bq.w);
            ffma2(acc[0][0], A0.x, b0); ffma2(acc[0][1], A0.x, b1);
            ffma2(acc[0][2], A0.x, b2); ffma2(acc[0][3], A0.x, b3);
            ffma2(acc[1][0], A0.y, b0); ffma2(acc[1][1], A0.y, b1);
            ffma2(acc[1][2], A0.y, b2); ffma2(acc[1][3], A0.y, b3);
            ffma2(acc[2][0], A1.x, b0); ffma2(acc[2][1], A1.x, b1);
            ffma2(acc[2][2], A1.x, b2); ffma2(acc[2][3], A1.x, b3);
            ffma2(acc[3][0], A1.y, b0); ffma2(acc[3][1], A1.y, b1);
            ffma2(acc[3][2], A1.y, b2); ffma2(acc[3][3], A1.y, b3);
        }
    }

    // extra frame (m0g-1)
    float fm1 = 0.f;
    if (tid < 64) {
#pragma unroll 11
        for (int fc = 0; fc < FC; fc++)
            fm1 += IDs[fc * 68 + tid] * yc[fc];
    }
    __syncthreads();

    // frames into aliased region: fsL[i][t] = R[i*68 + t]; fsL[0] = frame m0g-1
#pragma unroll
    for (int p = 0; p < 4; p++) {
        int j = r0 + 2 * p;
        LF q0, q1, q2, q3;
        q0.ll = acc[p][0]; q1.ll = acc[p][1]; q2.ll = acc[p][2]; q3.ll = acc[p][3];
        *(float4*)&R[(1 + j) * 68 + t0] = make_float4(q0.f2.x, q1.f2.x, q2.f2.x, q3.f2.x);
        *(float4*)&R[(2 + j) * 68 + t0] = make_float4(q0.f2.y, q1.f2.y, q2.f2.y, q3.f2.y);
    }
    if (tid < 64) R[tid] = fm1;
    __syncthreads();

    for (int sidx = tid; sidx < 4096; sidx += 256) {
        int i = sidx >> 5, r = sidx & 31;
        int m = m0g + i;
        int b = m / NFS;
        int n = m - b * NFS;
        if (n < 1 || n >= NFRAME) continue;
        float v = (R[(i + 1) * 68 + r] + R[i * 68 + r + 32]) * inv[r];
        out[((size_t)(b * COUT + o) << 14) + (n - 1) * 32 + r] = v;
    }
}

// =====================================================================
extern "C" void kernel_launch(void* const* d_in, const int* in_sizes, int n_in,
                              void* d_out, int out_size) {
    const float* x      = (const float*)d_in[0];
    const float* weight = (const float*)d_in[1];
    float* out          = (float*)d_out;
    (void)in_sizes; (void)n_in; (void)out_size;

    cudaFuncSetAttribute(k_mix_mma, cudaFuncAttributeMaxDynamicSharedMemorySize, MIX_SMEM);

    k_wprep<<<(NFREQ * COUT * CIN + 255) / 256, 256>>>(weight);
    k_stft <<<dim3(9, 32, 8), dim3(16, 18)>>>(x);
    k_mix_mma<<<dim3(C2 / 128, NFREQ), 256, MIX_SMEM>>>();
    k_frames_ola<<<dim3(MS / 128, COUT), dim3(16, 16)>>>(out);
}

// round 5
// speedup vs baseline: 2.2321x; 1.2288x over previous
#include <cuda_runtime.h>
#include <cuda_bf16.h>
#include <stdint.h>

// ---------------- problem constants ----------------
#define NFREQ  33
#define FC     66
#define FCP    80            // fc padded for K/N tiling
#define BATCH  8
#define CIN    64
#define COUT   64
#define TLEN   16384
#define NFRAME 513
#define NFS    576           // padded frames per batch (9*64)
#define MS     (BATCH*NFS)   // 4608 = 36*128

// ---------------- global scratch (zero-initialized) ----------------
__device__ __nv_bfloat16 g_Uh[(size_t)FC * CIN  * MS];
__device__ __nv_bfloat16 g_Ul[(size_t)FC * CIN  * MS];
__device__ __nv_bfloat16 g_Yh[(size_t)FC * COUT * MS];
__device__ __nv_bfloat16 g_Yl[(size_t)FC * COUT * MS];
__device__ __nv_bfloat16 g_Wh[(size_t)NFREQ * COUT * CIN];
__device__ __nv_bfloat16 g_Wl[(size_t)NFREQ * COUT * CIN];
__device__ __nv_bfloat16 g_Bth[FCP * 68], g_Btl[FCP * 68];   // [fc][t], rows 136B
__device__ __nv_bfloat16 g_IDh[64 * 82],  g_IDl[64 * 82];    // [t'][fc], rows 164B

__device__ __forceinline__ void mma_bf16(float* d, const uint32_t* a, const uint32_t* b) {
    asm volatile(
        "mma.sync.aligned.m16n8k16.row.col.f32.bf16.bf16.f32 "
        "{%0,%1,%2,%3}, {%4,%5,%6,%7}, {%8,%9}, {%0,%1,%2,%3};"
        : "+f"(d[0]), "+f"(d[1]), "+f"(d[2]), "+f"(d[3])
        : "r"(a[0]), "r"(a[1]), "r"(a[2]), "r"(a[3]), "r"(b[0]), "r"(b[1]));
}
// A fragment: [m][k] rows of `stride` bytes
__device__ __forceinline__ void ldA(uint32_t a[4], const char* base, int m,
                                    int k0, int g, int tig, int stride) {
    const char* p = base + (m + g) * stride + k0 * 2 + tig * 4;
    a[0] = *(const uint32_t*)p;
    a[1] = *(const uint32_t*)(p + 8 * stride);
    a[2] = *(const uint32_t*)(p + 16);
    a[3] = *(const uint32_t*)(p + 8 * stride + 16);
}
// B fragment: [n][k] rows of `stride` bytes
__device__ __forceinline__ void ldB(uint32_t b[2], const char* base, int n,
                                    int k0, int g, int tig, int stride) {
    const char* p = base + (n + g) * stride + k0 * 2 + tig * 4;
    b[0] = *(const uint32_t*)p;
    b[1] = *(const uint32_t*)(p + 16);
}
__device__ __forceinline__ void split2(float v, uint16_t& h, uint16_t& l) {
    __nv_bfloat16 hb = __float2bfloat16(v);
    __nv_bfloat16 lb = __float2bfloat16(v - __bfloat162float(hb));
    h = *(uint16_t*)&hb; l = *(uint16_t*)&lb;
}

// =====================================================================
// table precompute (runs every call; deterministic)
// =====================================================================
__global__ __launch_bounds__(256) void k_prep() {
    int tid0 = blockIdx.x * 256 + threadIdx.x;
    for (int idx = tid0; idx < FCP * 68; idx += 32 * 256) {
        int fc = idx / 68, t = idx - fc * 68;
        float v = 0.f;
        if (fc < FC && t < 64) {
            int f = fc >> 1;
            float s, c;
            sincospif((float)(f * t) / 32.0f, &s, &c);
            v = (fc & 1) ? -s : c;
            v *= 0.5f - 0.5f * cospif((float)t / 32.0f);
        }
        uint16_t h, l; split2(v, h, l);
        ((uint16_t*)g_Bth)[idx] = h; ((uint16_t*)g_Btl)[idx] = l;
    }
    for (int idx = tid0; idx < 64 * 82; idx += 32 * 256) {
        int t = idx / 82, fc = idx - t * 82;
        float v = 0.f;
        if (fc < FC) {
            int f = fc >> 1;
            float s, c;
            sincospif((float)(f * t) / 32.0f, &s, &c);
            float af = (f == 0 || f == 32) ? 1.0f : 2.0f;
            if (fc & 1) v = (f == 0 || f == 32) ? 0.f : -s * af;
            else        v = c * af;
            v *= (0.5f - 0.5f * cospif((float)t / 32.0f)) * (1.0f / 64.0f);
        }
        uint16_t h, l; split2(v, h, l);
        ((uint16_t*)g_IDh)[idx] = h; ((uint16_t*)g_IDl)[idx] = l;
    }
}

__global__ __launch_bounds__(256) void k_wprep(const float* __restrict__ weight) {
    int gid = blockIdx.x * 256 + threadIdx.x;
    if (gid >= NFREQ * COUT * CIN) return;
    int f = gid / (COUT * CIN);
    int rem = gid - f * (COUT * CIN);
    int o = rem >> 6, i = rem & 63;
    float w = weight[((size_t)o * CIN + i) * NFREQ + f];
    uint16_t h, l; split2(w, h, l);
    size_t dst = ((size_t)f * COUT + o) * CIN + i;
    ((uint16_t*)g_Wh)[dst] = h; ((uint16_t*)g_Wl)[dst] = l;
}

// =====================================================================
// Stage 1: STFT via mma.  D[m=c(128)][n=fc(80)], K=t(64).
// smem: AH@0 (128*140), AL@17920, BH@35840 (80*136), BL@46720; total 57600
// Dt (split output staging) aliases A: DtH@0 (66*264), DtL@17920
// =====================================================================
#define STFT_SMEM 57600
__global__ __launch_bounds__(256) void k_stft(const float* __restrict__ x) {
    extern __shared__ __align__(16) char SM[];
    const int tid = threadIdx.x, w = tid >> 5, lane = tid & 31;
    const int g = lane >> 2, tig = lane & 3;
    const int nch = blockIdx.x, i0 = blockIdx.y * 2, b = blockIdx.z;

    // build A (frames as split bf16, [c][t] rows 140B)
    const float* xr = x + ((size_t)(b * CIN + i0)) * TLEN;
    for (int idx = tid; idx < 8192; idx += 256) {
        int c = idx >> 6, t = idx & 63;
        int il = c >> 6, nl = c & 63;
        int src = nch * 2048 + nl * 32 + t - 32;
        src = src < 0 ? -src : src;
        src = src >= TLEN ? 2 * TLEN - 2 - src : src;
        float v = xr[(size_t)il * TLEN + src];
        uint16_t h, l; split2(v, h, l);
        *(uint16_t*)(SM + 0     + c * 140 + t * 2) = h;
        *(uint16_t*)(SM + 17920 + c * 140 + t * 2) = l;
    }
    // B tables
    {
        const uint32_t* bh = (const uint32_t*)g_Bth;
        const uint32_t* bl = (const uint32_t*)g_Btl;
        for (int idx = tid; idx < 2720; idx += 256) {
            *(uint32_t*)(SM + 35840 + idx * 4) = bh[idx];
            *(uint32_t*)(SM + 46720 + idx * 4) = bl[idx];
        }
    }
    __syncthreads();

    const int mb = (w & 3) * 32, nb = (w >> 2) * 40;
    float d[2][5][4];
#pragma unroll
    for (int r = 0; r < 2; r++)
#pragma unroll
        for (int nt = 0; nt < 5; nt++)
#pragma unroll
            for (int q = 0; q < 4; q++) d[r][nt][q] = 0.f;

#pragma unroll
    for (int kc = 0; kc < 4; kc++) {
        int k0 = kc * 16;
        uint32_t ah[2][4], al[2][4];
        ldA(ah[0], SM + 0, mb, k0, g, tig, 140);
        ldA(ah[1], SM + 0, mb + 16, k0, g, tig, 140);
        ldA(al[0], SM + 17920, mb, k0, g, tig, 140);
        ldA(al[1], SM + 17920, mb + 16, k0, g, tig, 140);
#pragma unroll
        for (int nt = 0; nt < 5; nt++) {
            uint32_t bh[2], bl[2];
            ldB(bh, SM + 35840, nb + nt * 8, k0, g, tig, 136);
            ldB(bl, SM + 46720, nb + nt * 8, k0, g, tig, 136);
#pragma unroll
            for (int r = 0; r < 2; r++) {
                mma_bf16(d[r][nt], ah[r], bh);
                mma_bf16(d[r][nt], al[r], bh);
                mma_bf16(d[r][nt], ah[r], bl);
            }
        }
    }
    __syncthreads();   // A dead; alias as Dt

    // Dt[fc][c] split staging
#pragma unroll
    for (int r = 0; r < 2; r++)
#pragma unroll
        for (int nt = 0; nt < 5; nt++) {
            int m = mb + r * 16 + g;
            int n = nb + nt * 8 + tig * 2;
            uint16_t h, l;
            if (n < FC) {
                split2(d[r][nt][0], h, l);
                *(uint16_t*)(SM + 0 + n * 264 + m * 2) = h;
                *(uint16_t*)(SM + 17920 + n * 264 + m * 2) = l;
                split2(d[r][nt][2], h, l);
                *(uint16_t*)(SM + 0 + n * 264 + (m + 8) * 2) = h;
                *(uint16_t*)(SM + 17920 + n * 264 + (m + 8) * 2) = l;
            }
            if (n + 1 < FC) {
                split2(d[r][nt][1], h, l);
                *(uint16_t*)(SM + 0 + (n + 1) * 264 + m * 2) = h;
                *(uint16_t*)(SM + 17920 + (n + 1) * 264 + m * 2) = l;
                split2(d[r][nt][3], h, l);
                *(uint16_t*)(SM + 0 + (n + 1) * 264 + (m + 8) * 2) = h;
                *(uint16_t*)(SM + 17920 + (n + 1) * 264 + (m + 8) * 2) = l;
            }
        }
    __syncthreads();

    // coalesced global write: rows (fc, i) of 64 frames (128 B)
    uint32_t* uh = (uint32_t*)g_Uh;
    uint32_t* ul = (uint32_t*)g_Ul;
    const size_t cb = (size_t)b * NFS + nch * 64;
    for (int idx = tid; idx < 4224; idx += 256) {
        int row = idx >> 5, wq = idx & 31;
        int fc = row >> 1, il = row & 1;
        uint32_t vh = *(uint32_t*)(SM + 0 + fc * 264 + il * 128 + wq * 4);
        uint32_t vl = *(uint32_t*)(SM + 17920 + fc * 264 + il * 128 + wq * 4);
        size_t di = ((((size_t)fc * CIN + i0 + il) * MS) + cb) >> 1;
        uh[di + wq] = vh;
        ul[di + wq] = vl;
    }
}

// =====================================================================
// Stage 2: mix via mma.  D[m=c(128)][n=o(64)], K=i(64), per fc.
// smem: AH@0 (128*140), AL@17920, WH@35840 (64*136), WL@44544; total 53248
// Dt aliases A: DtH@0 (64*264), DtL@17920
// =====================================================================
#define MIX_SMEM 53248
__global__ __launch_bounds__(256) void k_mix() {
    extern __shared__ __align__(16) char SM[];
    const int tid = threadIdx.x, w = tid >> 5, lane = tid & 31;
    const int g = lane >> 2, tig = lane & 3;
    const int fc = blockIdx.y, f = fc >> 1;
    const size_t c0 = (size_t)blockIdx.x * 128;

    // A: transpose-stage U rows -> [c][i]
    const uint32_t* uh = (const uint32_t*)g_Uh;
    const uint32_t* ul = (const uint32_t*)g_Ul;
    for (int idx = tid; idx < 4096; idx += 256) {
        int i = idx >> 6, cq = idx & 63;
        size_t si = ((((size_t)fc * CIN + i) * MS) + c0) / 2 + cq;
        uint32_t vh = uh[si], vl = ul[si];
        int c = cq * 2;
        *(uint16_t*)(SM + 0 + c * 140 + i * 2)       = (uint16_t)vh;
        *(uint16_t*)(SM + 0 + (c + 1) * 140 + i * 2) = (uint16_t)(vh >> 16);
        *(uint16_t*)(SM + 17920 + c * 140 + i * 2)       = (uint16_t)vl;
        *(uint16_t*)(SM + 17920 + (c + 1) * 140 + i * 2) = (uint16_t)(vl >> 16);
    }
    // B: W rows [o][i]
    {
        const uint32_t* wh = (const uint32_t*)g_Wh;
        const uint32_t* wl = (const uint32_t*)g_Wl;
        for (int idx = tid; idx < 2048; idx += 256) {
            int o = idx >> 5, wq = idx & 31;
            size_t si = ((size_t)f * COUT + o) * 32 + wq;
            *(uint32_t*)(SM + 35840 + o * 136 + wq * 4) = wh[si];
            *(uint32_t*)(SM + 44544 + o * 136 + wq * 4) = wl[si];
        }
    }
    __syncthreads();

    const int mb = (w & 3) * 32, nb = (w >> 2) * 32;
    float d[2][4][4];
#pragma unroll
    for (int r = 0; r < 2; r++)
#pragma unroll
        for (int nt = 0; nt < 4; nt++)
#pragma unroll
            for (int q = 0; q < 4; q++) d[r][nt][q] = 0.f;

#pragma unroll
    for (int kc = 0; kc < 4; kc++) {
        int k0 = kc * 16;
        uint32_t ah[2][4], al[2][4];
        ldA(ah[0], SM + 0, mb, k0, g, tig, 140);
        ldA(ah[1], SM + 0, mb + 16, k0, g, tig, 140);
        ldA(al[0], SM + 17920, mb, k0, g, tig, 140);
        ldA(al[1], SM + 17920, mb + 16, k0, g, tig, 140);
#pragma unroll
        for (int nt = 0; nt < 4; nt++) {
            uint32_t bh[2], bl[2];
            ldB(bh, SM + 35840, nb + nt * 8, k0, g, tig, 136);
            ldB(bl, SM + 44544, nb + nt * 8, k0, g, tig, 136);
#pragma unroll
            for (int r = 0; r < 2; r++) {
                mma_bf16(d[r][nt], ah[r], bh);
                mma_bf16(d[r][nt], al[r], bh);
                mma_bf16(d[r][nt], ah[r], bl);
            }
        }
    }
    __syncthreads();

    // Dt[o][c] split staging
#pragma unroll
    for (int r = 0; r < 2; r++)
#pragma unroll
        for (int nt = 0; nt < 4; nt++) {
            int m = mb + r * 16 + g;
            int n = nb + nt * 8 + tig * 2;
            uint16_t h, l;
            split2(d[r][nt][0], h, l);
            *(uint16_t*)(SM + 0 + n * 264 + m * 2) = h;
            *(uint16_t*)(SM + 17920 + n * 264 + m * 2) = l;
            split2(d[r][nt][1], h, l);
            *(uint16_t*)(SM + 0 + (n + 1) * 264 + m * 2) = h;
            *(uint16_t*)(SM + 17920 + (n + 1) * 264 + m * 2) = l;
            split2(d[r][nt][2], h, l);
            *(uint16_t*)(SM + 0 + n * 264 + (m + 8) * 2) = h;
            *(uint16_t*)(SM + 17920 + n * 264 + (m + 8) * 2) = l;
            split2(d[r][nt][3], h, l);
            *(uint16_t*)(SM + 0 + (n + 1) * 264 + (m + 8) * 2) = h;
            *(uint16_t*)(SM + 17920 + (n + 1) * 264 + (m + 8) * 2) = l;
        }
    __syncthreads();

    uint32_t* yh = (uint32_t*)g_Yh;
    uint32_t* yl = (uint32_t*)g_Yl;
    for (int idx = tid; idx < 4096; idx += 256) {
        int o = idx >> 6, wq = idx & 63;
        uint32_t vh = *(uint32_t*)(SM + 0 + o * 264 + wq * 4);
        uint32_t vl = *(uint32_t*)(SM + 17920 + o * 264 + wq * 4);
        size_t di = ((((size_t)fc * COUT + o) * MS) + c0) / 2 + wq;
        yh[di] = vh;
        yl[di] = vl;
    }
}

// =====================================================================
// Stage 3+4: ISTFT frames via mma + fused OLA.
// D[m=c(128)][n=t'(64)], K=fc(80).
// smem: YtH@0 (128*164), YtL@20992, IDH@41984 (64*164), IDL@52480; 62976
// F (frames fp32, 129*68) aliases Yt after mma.
// =====================================================================
#define FRAMES_SMEM 62976
__global__ __launch_bounds__(256) void k_frames_ola(float* __restrict__ out) {
    extern __shared__ __align__(16) char SM[];
    __shared__ float yc[FC];
    __shared__ float inv[32];
    const int tid = threadIdx.x, w = tid >> 5, lane = tid & 31;
    const int g = lane >> 2, tig = lane & 3;
    const int o = blockIdx.y;
    const size_t c0 = (size_t)blockIdx.x * 128;

    // stage Yt [c][fc] (transpose)
    const uint32_t* yh = (const uint32_t*)g_Yh;
    const uint32_t* yl = (const uint32_t*)g_Yl;
    for (int idx = tid; idx < 4224; idx += 256) {
        int fc = idx >> 6, cq = idx & 63;
        size_t si = ((((size_t)fc * COUT + o) * MS) + c0) / 2 + cq;
        uint32_t vh = yh[si], vl = yl[si];
        int c = cq * 2;
        *(uint16_t*)(SM + 0 + c * 164 + fc * 2)       = (uint16_t)vh;
        *(uint16_t*)(SM + 0 + (c + 1) * 164 + fc * 2) = (uint16_t)(vh >> 16);
        *(uint16_t*)(SM + 20992 + c * 164 + fc * 2)       = (uint16_t)vl;
        *(uint16_t*)(SM + 20992 + (c + 1) * 164 + fc * 2) = (uint16_t)(vl >> 16);
    }
    // zero pad fc 66..79
    for (int idx = tid; idx < 896; idx += 256) {
        int r = idx / 7, q = idx - r * 7;
        *(uint32_t*)(SM + 0 + r * 164 + 132 + q * 4) = 0;
        *(uint32_t*)(SM + 20992 + r * 164 + 132 + q * 4) = 0;
    }
    // ID tables
    {
        const uint32_t* ih = (const uint32_t*)g_IDh;
        const uint32_t* il = (const uint32_t*)g_IDl;
        for (int idx = tid; idx < 2624; idx += 256) {
            *(uint32_t*)(SM + 41984 + idx * 4) = ih[idx];
            *(uint32_t*)(SM + 52480 + idx * 4) = il[idx];
        }
    }
    if (tid < FC) {
        float v = 0.f;
        if (blockIdx.x > 0) {
            size_t ei = ((size_t)tid * COUT + o) * MS + c0 - 1;
            v = __bfloat162float(g_Yh[ei]) + __bfloat162float(g_Yl[ei]);
        }
        yc[tid] = v;
    }
    if (tid < 32) {
        float c = cospif((float)tid / 32.0f);
        float w1 = 0.5f - 0.5f * c, w2 = 0.5f + 0.5f * c;
        inv[tid] = 1.0f / (w1 * w1 + w2 * w2);
    }
    __syncthreads();

    const int mb = (w & 3) * 32, nb = (w >> 2) * 32;
    float d[2][4][4];
#pragma unroll
    for (int r = 0; r < 2; r++)
#pragma unroll
        for (int nt = 0; nt < 4; nt++)
#pragma unroll
            for (int q = 0; q < 4; q++) d[r][nt][q] = 0.f;

#pragma unroll
    for (int kc = 0; kc < 5; kc++) {
        int k0 = kc * 16;
        uint32_t ah[2][4], al[2][4];
        ldA(ah[0], SM + 0, mb, k0, g, tig, 164);
        ldA(ah[1], SM + 0, mb + 16, k0, g, tig, 164);
        ldA(al[0], SM + 20992, mb, k0, g, tig, 164);
        ldA(al[1], SM + 20992, mb + 16, k0, g, tig, 164);
#pragma unroll
        for (int nt = 0; nt < 4; nt++) {
            uint32_t bh[2], bl[2];
            ldB(bh, SM + 41984, nb + nt * 8, k0, g, tig, 164);
            ldB(bl, SM + 52480, nb + nt * 8, k0, g, tig, 164);
#pragma unroll
            for (int r = 0; r < 2; r++) {
                mma_bf16(d[r][nt], ah[r], bh);
                mma_bf16(d[r][nt], al[r], bh);
                mma_bf16(d[r][nt], ah[r], bl);
            }
        }
    }

    // boundary frame (c0-1), taps 32..63 only
    float fm = 0.f;
    if (tid < 32) {
        int t = 32 + tid;
#pragma unroll 11
        for (int q = 0; q < FC; q++) {
            float idv = __bfloat162float(*(__nv_bfloat16*)(SM + 41984 + t * 164 + q * 2))
                      + __bfloat162float(*(__nv_bfloat16*)(SM + 52480 + t * 164 + q * 2));
            fm += idv * yc[q];
        }
    }
    __syncthreads();   // Yt dead; alias as F

    float* F = (float*)SM;   // F[i][t'] rows of 68 floats; F[0] = frame c0-1
#pragma unroll
    for (int r = 0; r < 2; r++)
#pragma unroll
        for (int nt = 0; nt < 4; nt++) {
            int m = mb + r * 16 + g;
            int t = nb + nt * 8 + tig * 2;
            F[(1 + m) * 68 + t]     = d[r][nt][0];
            F[(1 + m) * 68 + t + 1] = d[r][nt][1];
            F[(9 + m) * 68 + t]     = d[r][nt][2];
            F[(9 + m) * 68 + t + 1] = d[r][nt][3];
        }
    if (tid < 32) F[32 + tid] = fm;
    __syncthreads();

    for (int sidx = tid; sidx < 4096; sidx += 256) {
        int i = sidx >> 5, r = sidx & 31;
        size_t m = c0 + i;
        int b = (int)(m / NFS);
        int n = (int)(m - (size_t)b * NFS);
        if (n < 1 || n >= NFRAME) continue;
        float v = (F[(i + 1) * 68 + r] + F[i * 68 + r + 32]) * inv[r];
        out[(((size_t)(b * COUT + o)) << 14) + (size_t)(n - 1) * 32 + r] = v;
    }
}

// =====================================================================
extern "C" void kernel_launch(void* const* d_in, const int* in_sizes, int n_in,
                              void* d_out, int out_size) {
    const float* x      = (const float*)d_in[0];
    const float* weight = (const float*)d_in[1];
    float* out          = (float*)d_out;
    (void)in_sizes; (void)n_in; (void)out_size;

    static int init = 0;
    if (!init) {
        cudaFuncSetAttribute(k_stft, cudaFuncAttributeMaxDynamicSharedMemorySize, STFT_SMEM);
        cudaFuncSetAttribute(k_mix, cudaFuncAttributeMaxDynamicSharedMemorySize, MIX_SMEM);
        cudaFuncSetAttribute(k_frames_ola, cudaFuncAttributeMaxDynamicSharedMemorySize, FRAMES_SMEM);
        init = 1;
    }

    k_wprep<<<(NFREQ * COUT * CIN + 255) / 256, 256>>>(weight);
    k_prep <<<32, 256>>>();
    k_stft <<<dim3(9, 32, 8), 256, STFT_SMEM>>>(x);
    k_mix  <<<dim3(36, FC), 256, MIX_SMEM>>>();
    k_frames_ola<<<dim3(36, COUT), 256, FRAMES_SMEM>>>(out);
}